// round 11
// baseline (speedup 1.0000x reference)
#include <cuda_runtime.h>
#include <cstdint>

#define BATCH   32
#define NPRED   22743
#define NCLS    80
#define KTOP    300
#define STRIDE  85
#define CAP     512
#define NBUCK   4096
#define RPC     2048    // rows per CTA (512 threads x 4)
#define NCTA1   12      // ceil(NPRED / RPC)

// global scratch — zero at module load; every pass restores its own zeros
__device__ unsigned int g_keys[BATCH * NPRED];
__device__ unsigned int g_hist[BATCH * NBUCK];
__device__ unsigned int g_done[BATCH];

__device__ __forceinline__ unsigned int bucket_of(unsigned int key) {
    // key in (0x3F000000, 0x3F800000]  (conf in (0.5, 1.0])
    return min((key - 0x3F000000u) >> 11, (unsigned)(NBUCK - 1));
}

__global__ __launch_bounds__(512)
void kAll(const float* __restrict__ p, const float* __restrict__ ancs,
          const float* __restrict__ fsz,
          float* __restrict__ outIds, float* __restrict__ outBoxes,
          float* __restrict__ outLabels, float* __restrict__ outScores) {
    const int b    = blockIdx.y;
    const int tid  = threadIdx.x;
    const int lane = tid & 31;
    const int wrp  = tid >> 5;

    // ===== main phase: conf scan, 4 outstanding loads per thread =====
    {
        const int n0 = blockIdx.x * RPC + tid;
        const float* base = p + (size_t)b * NPRED * STRIDE + 4;
        float x0 = -1.f, x1 = -1.f, x2 = -1.f, x3 = -1.f;
        if (n0        < NPRED) x0 = __ldg(base + (size_t)(n0       ) * STRIDE);
        if (n0 + 512  < NPRED) x1 = __ldg(base + (size_t)(n0 + 512 ) * STRIDE);
        if (n0 + 1024 < NPRED) x2 = __ldg(base + (size_t)(n0 + 1024) * STRIDE);
        if (n0 + 1536 < NPRED) x3 = __ldg(base + (size_t)(n0 + 1536) * STRIDE);
        float xs[4] = {x0, x1, x2, x3};
#pragma unroll
        for (int k = 0; k < 4; k++) {
            int n = n0 + k * 512;
            if (n < NPRED) {
                float x = xs[k];
                unsigned int key = 0;
                if (x > 0.0f) {
                    float c = 1.0f / (1.0f + expf(-x));
                    if (c > 0.5f) key = __float_as_uint(c);   // conf > THR_CONF
                }
                g_keys[b * NPRED + n] = key;
                if (key) atomicAdd(&g_hist[b * NBUCK + bucket_of(key)], 1u);
            }
        }
    }

    // ===== last-block election (deadlock-free) =====
    __shared__ int isLast;
    __threadfence();
    __syncthreads();
    if (tid == 0) isLast = (atomicAdd(&g_done[b], 1u) == NCTA1 - 1);
    __syncthreads();
    if (!isLast) return;
    __threadfence();   // acquire: all batch-b L2 writes visible

    // ===== tail (one CTA per batch): everything else in SMEM =====
    __shared__ __align__(16) unsigned long long cand[CAP];         // 4 KB, 16B-aligned
    __shared__ unsigned long long supp[KTOP][5];                   // 12 KB
    __shared__ float sl[KTOP], st[KTOP], sr[KTOP], sb[KTOP], sa[KTOP], ssc[KTOP];
    __shared__ int   sidx[KTOP], slab[KTOP];
    __shared__ unsigned long long anyLow[5], keepw[5];
    __shared__ unsigned int wsum[16], wsuf[17];
    __shared__ unsigned int sTotal;
    __shared__ int sT, scnt, scc;

    if (tid == 0) { scnt = 0; sTotal = 0; sT = 0; }
    if (tid < 5) anyLow[tid] = 0ull;
    if (tid < KTOP) { sidx[tid] = -1; }

    // ---- threshold: suffix scan over 4096 buckets (8 per thread) ----
    const unsigned int* h = g_hist + b * NBUCK;
    unsigned int v[8], s8 = 0;
#pragma unroll
    for (int i = 0; i < 8; i++) { v[i] = __ldg(h + tid * 8 + i); s8 += v[i]; }

    unsigned int suf = s8;
#pragma unroll
    for (int o = 1; o < 32; o <<= 1) {
        unsigned int t = __shfl_down_sync(0xffffffffu, suf, o);
        if (lane + o < 32) suf += t;
    }
    if (lane == 0) wsum[wrp] = suf;
    __syncthreads();
    if (wrp == 0) {
        unsigned int ws = (lane < 16) ? wsum[lane] : 0u;
#pragma unroll
        for (int o = 1; o < 32; o <<= 1) {
            unsigned int t = __shfl_down_sync(0xffffffffu, ws, o);
            if (lane + o < 32) ws += t;
        }
        if (lane < 16) wsuf[lane] = ws;
        if (lane == 0) { wsuf[16] = 0; sTotal = ws; }
    }
    __syncthreads();
    {
        unsigned int total = sTotal;
        unsigned int Kcap  = min((unsigned)KTOP, total);
        unsigned int inc   = suf + wsuf[wrp + 1];
        unsigned int above = inc - s8;
        if (Kcap > 0 && inc >= Kcap && above < Kcap) {
            unsigned int run = above;
            int T = tid * 8;
#pragma unroll
            for (int i = 7; i >= 0; i--) {
                run += v[i];
                if (run >= Kcap) { T = tid * 8 + i; break; }
            }
            sT = T;
        }
        if (Kcap == 0 && tid == 0) sT = NBUCK;
    }
    __syncthreads();
    const int T = sT;

    // ---- compaction into SMEM (~303 survivors), 4-way batched loads ----
    const unsigned int* kb = g_keys + (size_t)b * NPRED;
    for (int k0 = 0; k0 < 48; k0 += 4) {           // 48*512 >= NPRED
        unsigned int kv[4] = {0u, 0u, 0u, 0u};
#pragma unroll
        for (int j = 0; j < 4; j++) {
            int n = tid + (k0 + j) * 512;
            if (n < NPRED) kv[j] = __ldg(kb + n);
        }
#pragma unroll
        for (int j = 0; j < 4; j++) {
            unsigned int key = kv[j];
            if (key && (int)bucket_of(key) >= T) {
                int n = tid + (k0 + j) * 512;
                int pos = atomicAdd(&scnt, 1);
                if (pos < CAP)
                    cand[pos] = ((unsigned long long)key << 32) |
                                (0xFFFFFFFFu - (unsigned)n);
            }
        }
    }
    __syncthreads();
    const int cc = min(scnt, CAP);
    if (tid == 0) scc = cc;
    if (tid < CAP && tid >= cc) cand[tid] = 0ull;   // zero-fill tail
    __syncthreads();

    // ---- rank-scatter (vectorized LDS over cc entries only) ----
    if (tid < cc) {
        unsigned long long my = cand[tid];
        int cc4 = (cc + 3) & ~3;                     // cand[] zero beyond cc
        int rank = 0;
        for (int j = 0; j < cc4; j += 4) {
            ulonglong2 a = *reinterpret_cast<const ulonglong2*>(&cand[j]);
            ulonglong2 c2 = *reinterpret_cast<const ulonglong2*>(&cand[j + 2]);
            rank += (a.x > my) + (a.y > my) + (c2.x > my) + (c2.y > my);
        }
        if (rank < KTOP) {
            sidx[rank] = (int)(0xFFFFFFFFu - (unsigned int)(my & 0xFFFFFFFFull));
            ssc[rank]  = __uint_as_float((unsigned int)(my >> 32));
        }
    }
    __syncthreads();

    // ---- decode + class argmax: 64 groups x 8 lanes, 5 rounds ----
    {
        const int grp = tid >> 3;     // 0..63
        const int sub = tid & 7;
#pragma unroll
        for (int r = 0; r < 5; r++) {
            int i = r * 64 + grp;     // 0..319
            bool act = (i < KTOP) && (i < cc);
            int n = act ? sidx[i] : 0;
            const float* pr = p + ((size_t)b * NPRED + n) * STRIDE;
            unsigned long long best = 0ull;
            if (act) {
#pragma unroll
                for (int k = 0; k < 10; k++) {
                    int c = sub + k * 8;
                    unsigned int ub = __float_as_uint(__ldg(pr + 5 + c));
                    ub = (ub & 0x80000000u) ? ~ub : (ub | 0x80000000u);
                    unsigned long long key = ((unsigned long long)ub << 8) |
                                             (unsigned)(255 - c);
                    if (key > best) best = key;
                }
            }
            {
                unsigned long long t;
                t = __shfl_down_sync(0xffffffffu, best, 4, 8); if (t > best) best = t;
                t = __shfl_down_sync(0xffffffffu, best, 2, 8); if (t > best) best = t;
                t = __shfl_down_sync(0xffffffffu, best, 1, 8); if (t > best) best = t;
            }
            if (i < KTOP && sub == 0) {
                if (act) {
                    int label = 256 - (int)(best & 0xFFull);   // argmax + 1
                    float tx = __ldg(pr + 0), ty = __ldg(pr + 1);
                    float tw = __ldg(pr + 2), th = __ldg(pr + 3);
                    float fs = __ldg(fsz + (size_t)n * 2);
                    float4 an = *reinterpret_cast<const float4*>(ancs + (size_t)n * 4);
                    float cx = 1.0f / (1.0f + expf(-tx)) / fs + an.x;
                    float cy = 1.0f / (1.0f + expf(-ty)) / fs + an.y;
                    float w  = expf(tw) * an.z;
                    float hh = expf(th) * an.w;
                    float bl = cx - 0.5f * w,  bt = cy - 0.5f * hh;
                    float br = cx + 0.5f * w,  bbv = cy + 0.5f * hh;
                    *reinterpret_cast<float4*>(outBoxes + (size_t)(b * KTOP + i) * 4) =
                        make_float4(bl, bt, br, bbv);
                    float off = 4.0f * (float)label;
                    sl[i] = bl + off; st[i] = bt + off;
                    sr[i] = br + off; sb[i] = bbv + off;
                    sa[i] = fmaxf(br - bl, 0.0f) * fmaxf(bbv - bt, 0.0f);
                    slab[i] = label;
                } else {   // pad (never with this data)
                    *reinterpret_cast<float4*>(outBoxes + (size_t)(b * KTOP + i) * 4) =
                        make_float4(0.f, 0.f, 0.f, 0.f);
                    sl[i] = st[i] = sr[i] = sb[i] = sa[i] = 0.f;
                    ssc[i] = 0.f; slab[i] = 0;
                }
            }
        }
    }
    __syncthreads();

    // ---- suppression bitmask in SMEM: 1500 tasks over 512 threads ----
    for (int task = tid; task < KTOP * 5; task += 512) {
        int i = task % KTOP, w = task / KTOP;
        float li = sl[i], ti = st[i], ri = sr[i], bi = sb[i], ai = sa[i];
        unsigned long long bits = 0ull;
        int j0 = w * 64;
        int jend = min(j0 + 64, KTOP);
        for (int j = j0; j < jend; j++) {
            float ltx = fmaxf(li, sl[j]);
            float lty = fmaxf(ti, st[j]);
            float rbx = fminf(ri, sr[j]);
            float rby = fminf(bi, sb[j]);
            float iw = fmaxf(rbx - ltx, 0.0f);
            float ih = fmaxf(rby - lty, 0.0f);
            float inter = iw * ih;
            float iou = inter / (ai + sa[j] - inter + 1e-7f);
            if (iou > 0.3f) bits |= 1ull << (j - j0);
        }
        supp[i][w] = bits;
        unsigned long long low = 0ull;      // suppressors with j < i
        int iw6 = i >> 6;
        if (w < iw6)       low = bits;
        else if (w == iw6) low = bits & ((1ull << (i & 63)) - 1ull);
        if (low) atomicOr(&anyLow[iw6], 1ull << (i & 63));
    }
    __syncthreads();

    // ---- greedy scan (valid = rank < cc; registers only on fast path) ----
    if (tid == 0) {
        unsigned long long kw[5] = {0ull, 0ull, 0ull, 0ull, 0ull};
        int vcc = scc;
#pragma unroll
        for (int w = 0; w < 5; w++) {
            unsigned long long cur = 0ull;
            unsigned long long alw = anyLow[w];
            // valid bits in this word: ranks [w*64, min(cc,KTOP)) only
            int lo = w * 64;
            int hi = min(min(vcc, KTOP), lo + 64);
            unsigned long long vmw = 0ull;
            if (hi > lo) {
                int nb = hi - lo;
                vmw = (nb >= 64) ? ~0ull : ((1ull << nb) - 1ull);
            }
            int jend = (w < 4) ? 64 : (KTOP - 256);
            for (int jj = 0; jj < jend; jj++) {
                unsigned long long bit = 1ull << jj;
                if (vmw & bit) {
                    if (!(alw & bit)) {
                        cur |= bit;        // no lower-ranked overlap at all
                    } else {
                        int i = w * 64 + jj;
                        unsigned long long s = (supp[i][0] & kw[0]) |
                                               (supp[i][1] & kw[1]) |
                                               (supp[i][2] & kw[2]) |
                                               (supp[i][3] & kw[3]) |
                                               (supp[i][4] & kw[4]) |
                                               (supp[i][w] & cur);
                        if (s == 0ull) cur |= bit;
                    }
                }
            }
            kw[w] = cur;
        }
#pragma unroll
        for (int w = 0; w < 5; w++) keepw[w] = kw[w];
    }
    __syncthreads();

    // ---- final writes ----
    if (tid < KTOP) {
        bool kp = (keepw[tid >> 6] >> (tid & 63)) & 1ull;
        outIds[b * KTOP + tid]    = (float)b;
        outScores[b * KTOP + tid] = kp ? ssc[tid] : 0.0f;
        outLabels[b * KTOP + tid] = kp ? (float)slab[tid] : 0.0f;
    }

    // ---- restore zeros for next graph replay ----
    for (int i = tid; i < NBUCK; i += 512) g_hist[b * NBUCK + i] = 0u;
    if (tid == 0) g_done[b] = 0u;
}

// ---------------------------------------------------------------------------
extern "C" void kernel_launch(void* const* d_in, const int* in_sizes, int n_in,
                              void* d_out, int out_size) {
    const float* p    = (const float*)d_in[0];
    const float* ancs = (const float*)d_in[1];
    const float* fsz  = (const float*)d_in[2];
    float* out = (float*)d_out;

    float* outIds    = out;
    float* outBoxes  = out + BATCH * KTOP;
    float* outLabels = out + BATCH * KTOP * 5;
    float* outScores = out + BATCH * KTOP * 6;

    dim3 grid(NCTA1, BATCH);   // 12 x 32 CTAs
    kAll<<<grid, 512>>>(p, ancs, fsz, outIds, outBoxes, outLabels, outScores);
}

// round 12
// speedup vs baseline: 1.6645x; 1.6645x over previous
#include <cuda_runtime.h>
#include <cstdint>

#define BATCH   32
#define NPRED   22743
#define NCLS    80
#define KTOP    300
#define STRIDE  85
#define CAP     512
#define NBUCK   4096
#define RPC     2048    // rows per CTA in k1 (512 threads x 4)
#define NCTA1   12      // ceil(NPRED / RPC)

// global scratch — zero at module load; every pass restores its own zeros
__device__ unsigned int       g_keys[BATCH * NPRED];
__device__ unsigned int       g_hist[BATCH * NBUCK];
__device__ unsigned int       g_cnt[BATCH];
__device__ unsigned long long g_cand[BATCH * CAP];
__device__ float2             g_ls[BATCH * KTOP];        // (label, score) per rank
__device__ unsigned long long g_supp[BATCH * KTOP * 5];
__device__ unsigned long long g_anyLow[BATCH * 5];
__device__ unsigned int       g_done1[BATCH];            // last-block counters
__device__ unsigned int       g_done3[BATCH];

__device__ __forceinline__ unsigned int bucket_of(unsigned int key) {
    // key in (0x3F000000, 0x3F800000]  (conf in (0.5, 1.0])
    return min((key - 0x3F000000u) >> 11, (unsigned)(NBUCK - 1));
}

// ---------------------------------------------------------------------------
// k1: conf scan via cp.async (deep MLP, escapes the LDG miss-queue cap), then
// the last CTA per batch computes threshold + compaction + scratch re-zero.
// ---------------------------------------------------------------------------
__global__ __launch_bounds__(512) void k1(const float* __restrict__ p) {
    const int b    = blockIdx.y;
    const int tid  = threadIdx.x;
    const int lane = tid & 31;
    const int wrp  = tid >> 5;

    __shared__ float sbuf[RPC];   // 8 KB staging for cp.async

    // ---- phase 1: 4 cp.async per thread, all in flight simultaneously ----
    {
        const int n0 = blockIdx.x * RPC + tid;
        const float* base = p + (size_t)b * NPRED * STRIDE + 4;
#pragma unroll
        for (int k = 0; k < 4; k++) {
            int n = n0 + k * 512;
            if (n < NPRED) {
                unsigned int dst =
                    (unsigned int)__cvta_generic_to_shared(&sbuf[tid + k * 512]);
                const float* src = base + (size_t)n * STRIDE;
                asm volatile("cp.async.ca.shared.global [%0], [%1], 4;"
                             :: "r"(dst), "l"(src));
            }
        }
        asm volatile("cp.async.commit_group;");
        asm volatile("cp.async.wait_group 0;");
        // each thread consumes only its own slots — no __syncthreads needed
#pragma unroll
        for (int k = 0; k < 4; k++) {
            int n = n0 + k * 512;
            if (n < NPRED) {
                float x = sbuf[tid + k * 512];
                unsigned int key = 0;
                if (x > 0.0f) {
                    float c = 1.0f / (1.0f + expf(-x));
                    if (c > 0.5f) key = __float_as_uint(c);   // conf > THR_CONF
                }
                g_keys[b * NPRED + n] = key;
                if (key) atomicAdd(&g_hist[b * NBUCK + bucket_of(key)], 1u);
            }
        }
    }

    // ---- last-block election (deadlock-free: sole winner continues) ----
    __shared__ int isLast;
    __threadfence();
    __syncthreads();
    if (tid == 0) isLast = (atomicAdd(&g_done1[b], 1u) == NCTA1 - 1);
    __syncthreads();
    if (!isLast) return;
    __threadfence();   // acquire: all batch-b writes visible

    // ---- threshold: suffix scan over 4096 buckets ----
    __shared__ unsigned int wsum[16], wsuf[17];
    __shared__ unsigned int sTotal;
    __shared__ int sT, scnt;
    if (tid == 0) { scnt = 0; sTotal = 0; }

    const unsigned int* h = g_hist + b * NBUCK;
    unsigned int v[8], s8 = 0;
#pragma unroll
    for (int i = 0; i < 8; i++) { v[i] = __ldg(h + tid * 8 + i); s8 += v[i]; }

    unsigned int suf = s8;
#pragma unroll
    for (int o = 1; o < 32; o <<= 1) {
        unsigned int t = __shfl_down_sync(0xffffffffu, suf, o);
        if (lane + o < 32) suf += t;
    }
    if (lane == 0) wsum[wrp] = suf;
    __syncthreads();
    if (wrp == 0) {
        unsigned int ws = (lane < 16) ? wsum[lane] : 0u;
#pragma unroll
        for (int o = 1; o < 32; o <<= 1) {
            unsigned int t = __shfl_down_sync(0xffffffffu, ws, o);
            if (lane + o < 32) ws += t;
        }
        if (lane < 16) wsuf[lane] = ws;
        if (lane == 0) { wsuf[16] = 0; sTotal = ws; }
    }
    __syncthreads();
    {
        unsigned int total = sTotal;
        unsigned int Kcap  = min((unsigned)KTOP, total);
        unsigned int inc   = suf + wsuf[wrp + 1];
        unsigned int above = inc - s8;
        if (Kcap > 0 && inc >= Kcap && above < Kcap) {
            unsigned int run = above;
            int T = tid * 8;
#pragma unroll
            for (int i = 7; i >= 0; i--) {
                run += v[i];
                if (run >= Kcap) { T = tid * 8 + i; break; }
            }
            sT = T;
        }
        if (Kcap == 0 && tid == 0) sT = NBUCK;
    }
    __syncthreads();
    const int T = sT;

    // ---- compaction (~303 survivors), L2-hot keys, 4-way MLP ----
    const unsigned int* kb = g_keys + (size_t)b * NPRED;
    for (int k0 = 0; k0 < 48; k0 += 4) {           // 48*512 = 24576 >= NPRED
        unsigned int kv[4] = {0u, 0u, 0u, 0u};
#pragma unroll
        for (int j = 0; j < 4; j++) {
            int n = tid + (k0 + j) * 512;
            if (n < NPRED) kv[j] = __ldg(kb + n);
        }
#pragma unroll
        for (int j = 0; j < 4; j++) {
            unsigned int key = kv[j];
            if (key && (int)bucket_of(key) >= T) {
                int n = tid + (k0 + j) * 512;
                int pos = atomicAdd(&scnt, 1);
                if (pos < CAP)
                    g_cand[b * CAP + pos] = ((unsigned long long)key << 32) |
                                            (0xFFFFFFFFu - (unsigned)n);
            }
        }
    }
    __syncthreads();
    int cc = min(scnt, CAP);
    if (tid < CAP && tid >= cc) g_cand[b * CAP + tid] = 0ull;   // zero-fill tail
    if (tid == 0) g_cnt[b] = (unsigned)cc;

    // ---- restore zeros for next pass ----
    for (int i = tid; i < NBUCK; i += 512) g_hist[b * NBUCK + i] = 0u;
    if (tid == 0) g_done1[b] = 0u;
}

// ---------------------------------------------------------------------------
// k2: full-chip rank + decode + argmax. 512 threads = 64 groups of 8 lanes.
// ---------------------------------------------------------------------------
__global__ __launch_bounds__(512) void k2(const float* __restrict__ p,
                                          const float* __restrict__ ancs,
                                          const float* __restrict__ fsz,
                                          float* __restrict__ outBoxes) {
    const int chunk = blockIdx.x;       // 0..7
    const int b     = blockIdx.y;
    const int tid   = threadIdx.x;
    const int sub   = tid & 7;
    const int grp   = tid >> 3;         // 0..63
    const int slot  = chunk * 64 + grp; // 0..511

    __shared__ unsigned long long sc[CAP];
    sc[tid] = g_cand[b * CAP + tid];
    __syncthreads();

    unsigned long long my = sc[slot];

    int r = 0;
#pragma unroll 8
    for (int j = sub; j < CAP; j += 8) r += (sc[j] > my);
    r += __shfl_down_sync(0xffffffffu, r, 4, 8);
    r += __shfl_down_sync(0xffffffffu, r, 2, 8);
    r += __shfl_down_sync(0xffffffffu, r, 1, 8);
    r  = __shfl_sync(0xffffffffu, r, 0, 8);

    if (my != 0ull && r < KTOP) {
        int n = (int)(0xFFFFFFFFu - (unsigned int)(my & 0xFFFFFFFFull));
        const float* pr = p + ((size_t)b * NPRED + n) * STRIDE;

        unsigned long long best = 0ull;
#pragma unroll
        for (int k = 0; k < 10; k++) {
            int c = sub + k * 8;
            unsigned int ub = __float_as_uint(__ldg(pr + 5 + c));
            ub = (ub & 0x80000000u) ? ~ub : (ub | 0x80000000u);   // order-preserving
            unsigned long long key = ((unsigned long long)ub << 8) | (unsigned)(255 - c);
            if (key > best) best = key;
        }
        {
            unsigned long long t;
            t = __shfl_down_sync(0xffffffffu, best, 4, 8); if (t > best) best = t;
            t = __shfl_down_sync(0xffffffffu, best, 2, 8); if (t > best) best = t;
            t = __shfl_down_sync(0xffffffffu, best, 1, 8); if (t > best) best = t;
        }
        if (sub == 0) {
            int label = 256 - (int)(best & 0xFFull);   // argmax + 1, tie -> lowest
            float tx = __ldg(pr + 0), ty = __ldg(pr + 1);
            float tw = __ldg(pr + 2), th = __ldg(pr + 3);
            float fs = __ldg(fsz + (size_t)n * 2);
            float4 an = *reinterpret_cast<const float4*>(ancs + (size_t)n * 4);
            float cx = 1.0f / (1.0f + expf(-tx)) / fs + an.x;
            float cy = 1.0f / (1.0f + expf(-ty)) / fs + an.y;
            float w  = expf(tw) * an.z;
            float hh = expf(th) * an.w;
            *reinterpret_cast<float4*>(outBoxes + (size_t)(b * KTOP + r) * 4) =
                make_float4(cx - 0.5f * w, cy - 0.5f * hh, cx + 0.5f * w, cy + 0.5f * hh);
            g_ls[b * KTOP + r] =
                make_float2((float)label, __uint_as_float((unsigned int)(my >> 32)));
        }
    }
}

// ---------------------------------------------------------------------------
// k3: suppression bitmask (grid (5,32)); last CTA per batch runs the greedy
// scan + final writes + scratch resets.
// ---------------------------------------------------------------------------
__global__ __launch_bounds__(320) void k3(float* __restrict__ outBoxes,
                                          float* __restrict__ outIds,
                                          float* __restrict__ outLabels,
                                          float* __restrict__ outScores) {
    const int w   = blockIdx.x;     // 0..4
    const int b   = blockIdx.y;
    const int tid = threadIdx.x;

    __shared__ float sl[KTOP], st[KTOP], sr[KTOP], sb[KTOP], sa[KTOP];
    if (tid < KTOP) {
        float4 bx = *reinterpret_cast<const float4*>(outBoxes + (size_t)(b * KTOP + tid) * 4);
        float off = 4.0f * g_ls[b * KTOP + tid].x;
        float l = bx.x + off, t0 = bx.y + off, r = bx.z + off, bt = bx.w + off;
        sl[tid] = l; st[tid] = t0; sr[tid] = r; sb[tid] = bt;
        sa[tid] = fmaxf(r - l, 0.0f) * fmaxf(bt - t0, 0.0f);
    }
    __syncthreads();

    if (tid < KTOP) {
        const int i = tid;
        float li = sl[i], ti = st[i], ri = sr[i], bi = sb[i], ai = sa[i];
        unsigned long long bits = 0ull;
        int j0 = w * 64;
        int jend = min(j0 + 64, KTOP);
        for (int j = j0; j < jend; j++) {
            float ltx = fmaxf(li, sl[j]);
            float lty = fmaxf(ti, st[j]);
            float rbx = fminf(ri, sr[j]);
            float rby = fminf(bi, sb[j]);
            float iw = fmaxf(rbx - ltx, 0.0f);
            float ih = fmaxf(rby - lty, 0.0f);
            float inter = iw * ih;
            float iou = inter / (ai + sa[j] - inter + 1e-7f);
            if (iou > 0.3f) bits |= 1ull << (j - j0);
        }
        g_supp[(b * KTOP + i) * 5 + w] = bits;

        unsigned long long low = 0ull;     // suppressors with j < i
        int iw6 = i >> 6;
        if (w < iw6)       low = bits;
        else if (w == iw6) low = bits & ((1ull << (i & 63)) - 1ull);
        if (low) atomicOr(&g_anyLow[b * 5 + iw6], 1ull << (i & 63));
    }

    // ---- last-block election ----
    __shared__ int isLast;
    __threadfence();
    __syncthreads();
    if (tid == 0) isLast = (atomicAdd(&g_done3[b], 1u) == 4);
    __syncthreads();
    if (!isLast) return;
    __threadfence();   // acquire

    // ---- greedy scan (one CTA per batch) ----
    __shared__ unsigned long long ssup[KTOP * 5];   // 12 KB
    __shared__ float ssc[KTOP];
    __shared__ int   slab[KTOP];
    __shared__ unsigned long long validw[5], keepw[5];

    if (tid < 5) validw[tid] = 0ull;
    for (int t = tid; t < KTOP * 5; t += 320)
        ssup[t] = g_supp[b * (KTOP * 5) + t];

    int cc = min((int)g_cnt[b], KTOP);
    if (tid < KTOP) {
        if (tid < cc) {
            float2 ls = g_ls[b * KTOP + tid];
            ssc[tid]  = ls.y;
            slab[tid] = (int)ls.x;
        } else {   // pathological pad (never with this data)
            ssc[tid] = 0.0f; slab[tid] = 0;
            *reinterpret_cast<float4*>(outBoxes + (size_t)(b * KTOP + tid) * 4) =
                make_float4(0.f, 0.f, 0.f, 0.f);
        }
    }
    __syncthreads();
    if (tid < KTOP && ssc[tid] > 0.5f)
        atomicOr(&validw[tid >> 6], 1ull << (tid & 63));
    __syncthreads();

    if (tid == 0) {
        unsigned long long kw[5] = {0ull, 0ull, 0ull, 0ull, 0ull};
#pragma unroll
        for (int ww = 0; ww < 5; ww++) {
            unsigned long long cur = 0ull;
            unsigned long long alw = g_anyLow[b * 5 + ww];
            unsigned long long vmw = validw[ww];
            int jend = (ww < 4) ? 64 : (KTOP - 256);
            for (int jj = 0; jj < jend; jj++) {
                unsigned long long bit = 1ull << jj;
                if (vmw & bit) {
                    if (!(alw & bit)) {
                        cur |= bit;       // no lower-ranked overlap at all
                    } else {
                        int i = ww * 64 + jj;
                        unsigned long long s = (ssup[i * 5 + 0] & kw[0]) |
                                               (ssup[i * 5 + 1] & kw[1]) |
                                               (ssup[i * 5 + 2] & kw[2]) |
                                               (ssup[i * 5 + 3] & kw[3]) |
                                               (ssup[i * 5 + 4] & kw[4]) |
                                               (ssup[i * 5 + ww] & cur);
                        if (s == 0ull) cur |= bit;
                    }
                }
            }
            kw[ww] = cur;
        }
#pragma unroll
        for (int ww = 0; ww < 5; ww++) keepw[ww] = kw[ww];
    }
    __syncthreads();

    if (tid < KTOP) {
        bool kp = (keepw[tid >> 6] >> (tid & 63)) & 1ull;
        outIds[b * KTOP + tid]    = (float)b;
        outScores[b * KTOP + tid] = kp ? ssc[tid] : 0.0f;
        outLabels[b * KTOP + tid] = kp ? (float)slab[tid] : 0.0f;
    }

    // ---- restore zeros for next pass ----
    if (tid < 5)  g_anyLow[b * 5 + tid] = 0ull;
    if (tid == 0) g_done3[b] = 0u;
}

// ---------------------------------------------------------------------------
extern "C" void kernel_launch(void* const* d_in, const int* in_sizes, int n_in,
                              void* d_out, int out_size) {
    const float* p    = (const float*)d_in[0];
    const float* ancs = (const float*)d_in[1];
    const float* fsz  = (const float*)d_in[2];
    float* out = (float*)d_out;

    float* outIds    = out;
    float* outBoxes  = out + BATCH * KTOP;
    float* outLabels = out + BATCH * KTOP * 5;
    float* outScores = out + BATCH * KTOP * 6;

    dim3 grid1(NCTA1, BATCH);      // 12 x 32
    k1<<<grid1, 512>>>(p);
    dim3 grid2(CAP / 64, BATCH);   // 8 x 32
    k2<<<grid2, 512>>>(p, ancs, fsz, outBoxes);
    dim3 grid3(5, BATCH);          // 5 x 32
    k3<<<grid3, 320>>>(outBoxes, outIds, outLabels, outScores);
}